// round 15
// baseline (speedup 1.0000x reference)
#include <cuda_runtime.h>
#include <cstdint>

#define N_ATOMS 65536
#define ATOM_FDIM 133
#define BOND_TOTAL 147
#define BOND_FDIM 14
#define HIDDEN 256
#define MAX_NB 6
#define N_MOLS 2048
#define AF_LD 136              // padded atom_features stride
#define XH_LD 272              // padded Wh-input width (K for GEMM 2/3)
#define XO_LD 392              // padded Wo-input width (K for GEMM 4)
#define KW_OFF_WI 0
#define KW_OFF_WH (136 * 256)
#define KW_OFF_WO (408 * 256)  // 136 + 272
#define KW_ROWS 800            // 136 + 272 + 392

// ---------------- scratch (static device globals; no allocation) ----------------
__device__ float g_inp[(size_t)N_ATOMS * HIDDEN];
__device__ float g_msg[(size_t)N_ATOMS * HIDDEN];
__device__ float g_hid[(size_t)N_ATOMS * HIDDEN];
__device__ float g_Xhi[(size_t)N_ATOMS * XO_LD];
__device__ float g_Xlo[(size_t)N_ATOMS * XO_LD];
__device__ float g_afhi[(size_t)N_ATOMS * AF_LD];
__device__ float g_aflo[(size_t)N_ATOMS * AF_LD];
__device__ float g_Whi[(size_t)KW_ROWS * 256];
__device__ float g_Wlo[(size_t)KW_ROWS * 256];

// ---------------- helpers ----------------
__device__ __forceinline__ void cp_async16(uint32_t dst, const void* src) {
    asm volatile("cp.async.cg.shared.global [%0], [%1], 16;\n" :: "r"(dst), "l"(src));
}
__device__ __forceinline__ void cp_commit() { asm volatile("cp.async.commit_group;\n"); }
template <int N>
__device__ __forceinline__ void cp_wait() { asm volatile("cp.async.wait_group %0;\n" :: "n"(N)); }

__device__ __forceinline__ uint32_t f2tf32(float x) {
    uint32_t r;
    asm("cvt.rna.tf32.f32 %0, %1;" : "=r"(r) : "f"(x));
    return r;
}
__device__ __forceinline__ void split2(float v, float& hi, float& lo) {
    uint32_t h = f2tf32(v);
    hi = __uint_as_float(h);
    lo = __uint_as_float(f2tf32(v - __uint_as_float(h)));
}

__device__ __forceinline__ void mma_tf32(float* c, const uint32_t* a, const uint32_t* b) {
    asm("mma.sync.aligned.m16n8k8.row.col.f32.tf32.tf32.f32 "
        "{%0,%1,%2,%3}, {%4,%5,%6,%7}, {%8,%9}, {%0,%1,%2,%3};\n"
        : "+f"(c[0]), "+f"(c[1]), "+f"(c[2]), "+f"(c[3])
        : "r"(a[0]), "r"(a[1]), "r"(a[2]), "r"(a[3]), "r"(b[0]), "r"(b[1]));
}

// ---------------- prep: split weights into hi/lo with pad/remap ----------------
// dst row r -> src row: r<s1 ? r : (r>=s2 ? r-(s2-s1) : ZERO)
__global__ __launch_bounds__(256) void prep_w(
    const float* __restrict__ src, float* __restrict__ hi, float* __restrict__ lo,
    int s1, int s2, int rows)
{
    const int idx = blockIdx.x * 256 + threadIdx.x;
    if (idx >= rows * 256) return;
    const int r = idx >> 8, c = idx & 255;
    const int sr = (r < s1) ? r : ((r >= s2) ? r - (s2 - s1) : -1);
    const float v = (sr >= 0) ? src[sr * 256 + c] : 0.f;
    float h, l; split2(v, h, l);
    hi[idx] = h; lo[idx] = l;
}

// ---------------- prep: split atom_features (pad 133 -> 136) -------------------
__global__ __launch_bounds__(256) void prep_af(
    const float* __restrict__ af, float* __restrict__ hi, float* __restrict__ lo)
{
    const int idx = blockIdx.x * 256 + threadIdx.x;
    if (idx >= N_ATOMS * AF_LD) return;
    const int r = idx / AF_LD, c = idx - r * AF_LD;
    const float v = (c < ATOM_FDIM) ? af[r * ATOM_FDIM + c] : 0.f;
    float h, l; split2(v, h, l);
    hi[idx] = h; lo[idx] = l;
}

// ---------------- tensor-core GEMM (split-TF32, pre-split operands) -------------
// C[M,256] = (Ahi+Alo)[M,K] @ (Bhi+Blo)[K,256] + bias
// MODE 0: C0 = v; C1 = relu(v).  MODE 1: C1 = relu(inp + v).  MODE 2: C0 = relu(v).
// Block tile 128x128, BK=8, 8 warps (warp tile 64x32), 2-stage cp.async pipeline.
// A stride == K; K % 8 == 0; B buffer has exactly K rows (pads pre-zeroed).
template <int MODE>
__global__ __launch_bounds__(256) void gemm_tc(
    const float* __restrict__ Ahi, const float* __restrict__ Alo, int K,
    const float* __restrict__ Bhi, const float* __restrict__ Blo,
    const float* __restrict__ bias, const float* __restrict__ inp,
    float* __restrict__ C0, float* __restrict__ C1)
{
    __shared__ __align__(16) float As[2][2][128 * 8];   // [stage][hi/lo]
    __shared__ __align__(16) float Bs[2][2][8 * 128];

    const int tid = threadIdx.x;
    const int lane = tid & 31;
    const int warp = tid >> 5;
    const int wm = (warp & 1) * 64;
    const int wn = (warp >> 1) * 32;
    const int bx = blockIdx.x;      // N half (0/1)
    const int by = blockIdx.y;      // M tile

    const uint32_t asBase = (uint32_t)__cvta_generic_to_shared(&As[0][0][0]);
    const uint32_t bsBase = (uint32_t)__cvta_generic_to_shared(&Bs[0][0][0]);

    // loader coords: A 128x8 tile (1 float4/thread/array), B 8x128 (1 float4/thread/array)
    const int lm = tid >> 1;               // A row
    const int lg = tid & 1;                // A granule (0/1)
    const int lr = tid >> 5;               // B row (0..7)
    const int ln0 = (tid & 31) * 4;        // B col base
    const int agx = (lg ^ ((lm >> 2) & 1)) * 4;      // swizzled A granule offset
    const int bnx = ln0 ^ ((lr & 3) << 3);           // swizzled B col

    const size_t aRow = (size_t)(by * 128 + lm) * K;
    const uint32_t aDst = asBase + (uint32_t)(lm * 8 + agx) * 4;
    const uint32_t bDst = bsBase + (uint32_t)(lr * 128 + bnx) * 4;
    const int bCol = bx * 128 + ln0;

    auto load_chunk = [&](int k0, int buf) {
        cp_async16(aDst + (uint32_t)(buf * 2 + 0) * 4096, Ahi + aRow + k0 + lg * 4);
        cp_async16(aDst + (uint32_t)(buf * 2 + 1) * 4096, Alo + aRow + k0 + lg * 4);
        const size_t bOff = (size_t)(k0 + lr) * 256 + bCol;
        cp_async16(bDst + (uint32_t)(buf * 2 + 0) * 4096, Bhi + bOff);
        cp_async16(bDst + (uint32_t)(buf * 2 + 1) * 4096, Blo + bOff);
    };

    float acc[4][4][4];
#pragma unroll
    for (int i = 0; i < 4; i++)
#pragma unroll
        for (int j = 0; j < 4; j++)
#pragma unroll
            for (int v = 0; v < 4; v++) acc[i][j][v] = 0.f;

    const int nchunks = K >> 3;

    load_chunk(0, 0);
    cp_commit();

    const int kk = lane & 3;
    const int qrow = lane >> 2;

    for (int ch = 0; ch < nchunks; ch++) {
        const int buf = ch & 1;
        if (ch + 1 < nchunks) {
            load_chunk((ch + 1) * 8, buf ^ 1);
            cp_commit();
            cp_wait<1>();
        } else {
            cp_wait<0>();
        }
        __syncthreads();

        const float* AsH = &As[buf][0][0];
        const float* AsL = &As[buf][1][0];
        const float* BsH = &Bs[buf][0][0];
        const float* BsL = &Bs[buf][1][0];

        uint32_t afh[4][4], afl[4][4], bfh[4][2], bfl[4][2];
#pragma unroll
        for (int mt = 0; mt < 4; mt++) {
            const int row = wm + mt * 16 + qrow;         // row and row+8 share swizzle bit
            const int b = (row >> 2) & 1;
            const int o0 = row * 8 + ((0 ^ b) * 4) + kk; // k = kk
            const int o1 = row * 8 + ((1 ^ b) * 4) + kk; // k = kk+4
            afh[mt][0] = __float_as_uint(AsH[o0]);
            afh[mt][1] = __float_as_uint(AsH[o0 + 64]);
            afh[mt][2] = __float_as_uint(AsH[o1]);
            afh[mt][3] = __float_as_uint(AsH[o1 + 64]);
            afl[mt][0] = __float_as_uint(AsL[o0]);
            afl[mt][1] = __float_as_uint(AsL[o0 + 64]);
            afl[mt][2] = __float_as_uint(AsL[o1]);
            afl[mt][3] = __float_as_uint(AsL[o1 + 64]);
        }
        const int sw = kk << 3;
#pragma unroll
        for (int nt = 0; nt < 4; nt++) {
            const int n = (wn + nt * 8 + qrow) ^ sw;
            bfh[nt][0] = __float_as_uint(BsH[kk * 128 + n]);
            bfh[nt][1] = __float_as_uint(BsH[(kk + 4) * 128 + n]);
            bfl[nt][0] = __float_as_uint(BsL[kk * 128 + n]);
            bfl[nt][1] = __float_as_uint(BsL[(kk + 4) * 128 + n]);
        }
#pragma unroll
        for (int mt = 0; mt < 4; mt++)
#pragma unroll
            for (int nt = 0; nt < 4; nt++) {
                mma_tf32(acc[mt][nt], afl[mt], bfh[nt]);   // small terms first
                mma_tf32(acc[mt][nt], afh[mt], bfl[nt]);
                mma_tf32(acc[mt][nt], afh[mt], bfh[nt]);
            }
        __syncthreads();
    }

    // -------- epilogue --------
#pragma unroll
    for (int mt = 0; mt < 4; mt++) {
        const int r0 = by * 128 + wm + mt * 16 + qrow;
#pragma unroll
        for (int nt = 0; nt < 4; nt++) {
            const int co = bx * 128 + wn + nt * 8 + 2 * kk;
            const float2 bv = *reinterpret_cast<const float2*>(bias + co);
#pragma unroll
            for (int half = 0; half < 2; half++) {
                const int r = r0 + half * 8;
                const size_t base = (size_t)r * HIDDEN + co;
                float v0 = acc[mt][nt][half * 2 + 0] + bv.x;
                float v1 = acc[mt][nt][half * 2 + 1] + bv.y;
                if (MODE == 0) {
                    *reinterpret_cast<float2*>(C0 + base) = make_float2(v0, v1);
                    *reinterpret_cast<float2*>(C1 + base) =
                        make_float2(fmaxf(v0, 0.f), fmaxf(v1, 0.f));
                } else if (MODE == 1) {
                    const float2 iv = *reinterpret_cast<const float2*>(inp + base);
                    *reinterpret_cast<float2*>(C1 + base) =
                        make_float2(fmaxf(iv.x + v0, 0.f), fmaxf(iv.y + v1, 0.f));
                } else {
                    *reinterpret_cast<float2*>(C0 + base) =
                        make_float2(fmaxf(v0, 0.f), fmaxf(v1, 0.f));
                }
            }
        }
    }
}

// ---------------- gather for Wh input: writes split Xhi/Xlo (stride XH_LD) ------
__global__ __launch_bounds__(256) void gather_h_kernel(
    const float* __restrict__ msg, const float* __restrict__ f_bonds,
    const int* __restrict__ a2a, const int* __restrict__ a2b,
    float* __restrict__ Xhi, float* __restrict__ Xlo)
{
    const int i = blockIdx.x * 4 + (threadIdx.x >> 6);
    const int c4 = threadIdx.x & 63;
    int n[MAX_NB];
#pragma unroll
    for (int j = 0; j < MAX_NB; j++) n[j] = a2a[i * MAX_NB + j];

    float4 acc = make_float4(0.f, 0.f, 0.f, 0.f);
#pragma unroll
    for (int j = 0; j < MAX_NB; j++) {
        const float4 v = *reinterpret_cast<const float4*>(msg + (size_t)n[j] * HIDDEN + c4 * 4);
        acc.x += v.x; acc.y += v.y; acc.z += v.z; acc.w += v.w;
    }
    float4 h4, l4;
    split2(acc.x, h4.x, l4.x); split2(acc.y, h4.y, l4.y);
    split2(acc.z, h4.z, l4.z); split2(acc.w, h4.w, l4.w);
    *reinterpret_cast<float4*>(Xhi + (size_t)i * XH_LD + c4 * 4) = h4;
    *reinterpret_cast<float4*>(Xlo + (size_t)i * XH_LD + c4 * 4) = l4;

    if (c4 < BOND_FDIM) {
        float bs = 0.f;
#pragma unroll
        for (int j = 0; j < MAX_NB; j++) {
            int b = a2b[i * MAX_NB + j];
            bs += f_bonds[(size_t)b * BOND_TOTAL + (BOND_TOTAL - BOND_FDIM) + c4];
        }
        float h, l; split2(bs, h, l);
        Xhi[(size_t)i * XH_LD + HIDDEN + c4] = h;
        Xlo[(size_t)i * XH_LD + HIDDEN + c4] = l;
    }
    if (c4 < 2) {
        Xhi[(size_t)i * XH_LD + 270 + c4] = 0.f;
        Xlo[(size_t)i * XH_LD + 270 + c4] = 0.f;
    }
}

// ---------------- gather for Wo input: split af copy + split msg-sum ------------
// X cols 0..135 = prepped af hi/lo (incl. zero pad), cols 136..391 = msg-sum.
__global__ __launch_bounds__(256) void gather_o_kernel(
    const float* __restrict__ msg,
    const float* __restrict__ afhi, const float* __restrict__ aflo,
    const int* __restrict__ a2a,
    float* __restrict__ Xhi, float* __restrict__ Xlo)
{
    const int i = blockIdx.x * 4 + (threadIdx.x >> 6);
    const int c4 = threadIdx.x & 63;

    if (c4 < AF_LD / 4) {
        *reinterpret_cast<float4*>(Xhi + (size_t)i * XO_LD + c4 * 4) =
            *reinterpret_cast<const float4*>(afhi + (size_t)i * AF_LD + c4 * 4);
        *reinterpret_cast<float4*>(Xlo + (size_t)i * XO_LD + c4 * 4) =
            *reinterpret_cast<const float4*>(aflo + (size_t)i * AF_LD + c4 * 4);
    }

    int n[MAX_NB];
#pragma unroll
    for (int j = 0; j < MAX_NB; j++) n[j] = a2a[i * MAX_NB + j];
    float4 acc = make_float4(0.f, 0.f, 0.f, 0.f);
#pragma unroll
    for (int j = 0; j < MAX_NB; j++) {
        const float4 v = *reinterpret_cast<const float4*>(msg + (size_t)n[j] * HIDDEN + c4 * 4);
        acc.x += v.x; acc.y += v.y; acc.z += v.z; acc.w += v.w;
    }
    float4 h4, l4;
    split2(acc.x, h4.x, l4.x); split2(acc.y, h4.y, l4.y);
    split2(acc.z, h4.z, l4.z); split2(acc.w, h4.w, l4.w);
    *reinterpret_cast<float4*>(Xhi + (size_t)i * XO_LD + AF_LD + c4 * 4) = h4;
    *reinterpret_cast<float4*>(Xlo + (size_t)i * XO_LD + AF_LD + c4 * 4) = l4;
}

// ---------------- segment mean (sorted segment_ids) ----------------
__global__ __launch_bounds__(256) void seg_mean_kernel(
    const float* __restrict__ hid, const int* __restrict__ seg,
    float* __restrict__ out)
{
    const int m = blockIdx.x;
    __shared__ int s_lo, s_hi;
    if (threadIdx.x == 0) {
        int lo = 0, hi = N_ATOMS;
        while (lo < hi) { int mid = (lo + hi) >> 1; if (seg[mid] < m) lo = mid + 1; else hi = mid; }
        s_lo = lo;
        hi = N_ATOMS;
        while (lo < hi) { int mid = (lo + hi) >> 1; if (seg[mid] < m + 1) lo = mid + 1; else hi = mid; }
        s_hi = lo;
    }
    __syncthreads();
    const int lo = s_lo, hi = s_hi, c = threadIdx.x;
    float accv = 0.f;
    for (int a = lo; a < hi; a++) accv += hid[(size_t)a * HIDDEN + c];
    const int cnt = hi - lo;
    out[(size_t)m * HIDDEN + c] = (cnt > 0) ? accv / (float)cnt : 0.f;
}

// ---------------- launch -----------------------------------------------------
extern "C" void kernel_launch(void* const* d_in, const int* in_sizes, int n_in,
                              void* d_out, int out_size)
{
    const float* atom_features = (const float*)d_in[0];
    const float* f_bonds       = (const float*)d_in[1];
    const int*   a2a           = (const int*)  d_in[2];
    const int*   a2b           = (const int*)  d_in[3];
    const int*   segment_ids   = (const int*)  d_in[4];
    const float* Wi            = (const float*)d_in[5];
    const float* bi            = (const float*)d_in[6];
    const float* Wh            = (const float*)d_in[7];
    const float* bh            = (const float*)d_in[8];
    const float* Wo            = (const float*)d_in[9];
    const float* bo            = (const float*)d_in[10];
    float* out = (float*)d_out;

    float *inp, *msg, *hid, *Xhi, *Xlo, *afhi, *aflo, *Whi, *Wlo;
    cudaGetSymbolAddress((void**)&inp,  g_inp);
    cudaGetSymbolAddress((void**)&msg,  g_msg);
    cudaGetSymbolAddress((void**)&hid,  g_hid);
    cudaGetSymbolAddress((void**)&Xhi,  g_Xhi);
    cudaGetSymbolAddress((void**)&Xlo,  g_Xlo);
    cudaGetSymbolAddress((void**)&afhi, g_afhi);
    cudaGetSymbolAddress((void**)&aflo, g_aflo);
    cudaGetSymbolAddress((void**)&Whi,  g_Whi);
    cudaGetSymbolAddress((void**)&Wlo,  g_Wlo);

    const dim3 ggrid(2, N_ATOMS / 128);

    // one-time splits (cheap; rerun every call for determinism)
    prep_af<<<(N_ATOMS * AF_LD + 255) / 256, 256>>>(atom_features, afhi, aflo);
    prep_w<<<(136 * 256 + 255) / 256, 256>>>(Wi, Whi + KW_OFF_WI, Wlo + KW_OFF_WI, 133, 136, 136);
    prep_w<<<(272 * 256 + 255) / 256, 256>>>(Wh, Whi + KW_OFF_WH, Wlo + KW_OFF_WH, 270, 272, 272);
    prep_w<<<(392 * 256 + 255) / 256, 256>>>(Wo, Whi + KW_OFF_WO, Wlo + KW_OFF_WO, 133, 136, 392);

    // G1: inp = af @ Wi + bi ; msg = relu(inp)
    gemm_tc<0><<<ggrid, 256>>>(afhi, aflo, AF_LD, Whi + KW_OFF_WI, Wlo + KW_OFF_WI,
                               bi, nullptr, inp, msg);

    for (int d = 0; d < 2; d++) {
        gather_h_kernel<<<N_ATOMS / 4, 256>>>(msg, f_bonds, a2a, a2b, Xhi, Xlo);
        gemm_tc<1><<<ggrid, 256>>>(Xhi, Xlo, XH_LD, Whi + KW_OFF_WH, Wlo + KW_OFF_WH,
                                   bh, inp, nullptr, msg);
    }

    gather_o_kernel<<<N_ATOMS / 4, 256>>>(msg, afhi, aflo, a2a, Xhi, Xlo);
    gemm_tc<2><<<ggrid, 256>>>(Xhi, Xlo, XO_LD, Whi + KW_OFF_WO, Wlo + KW_OFF_WO,
                               bo, nullptr, hid, nullptr);

    seg_mean_kernel<<<N_MOLS, 256>>>(hid, segment_ids, out);
}